// round 2
// baseline (speedup 1.0000x reference)
#include <cuda_runtime.h>
#include <cstdint>

// ---------------- problem constants ----------------
#define C_CH    321
#define D_K     512
#define P_OUT   720
#define N_B     64          // batch == GEMM M
#define BN      128         // p-tile == GEMM N
#define BK      32          // k-chunk
#define KCHUNKS (D_K / BK)  // 16
#define STAGES  3

// ---------------- smem layout (floats, padded strides for bank-conflict-free frags) --
#define A_STRIDE 36                       // 64 rows x 36 floats
#define B_STRIDE 136                      // 32 rows x 136 floats
#define A_STAGE_BYTES (N_B * A_STRIDE * 4)   //  9216
#define B_STAGE_BYTES (BK * B_STRIDE * 4)    // 17408
#define B_BASE        (STAGES * A_STAGE_BYTES)              // 27648
#define SMEM_BYTES    (B_BASE + STAGES * B_STAGE_BYTES)     // 79872

// ---------------- helpers ----------------
__device__ __forceinline__ uint32_t smem_to_u32(const void* p) {
    uint32_t a;
    asm("{ .reg .u64 t; cvta.to.shared.u64 t, %1; cvt.u32.u64 %0, t; }" : "=r"(a) : "l"(p));
    return a;
}
__device__ __forceinline__ uint32_t f2tf32(float f) {
    uint32_t u;
    asm("cvt.rna.tf32.f32 %0, %1;" : "=r"(u) : "f"(f));
    return u;
}
#define CP_ASYNC16(dst, src) \
    asm volatile("cp.async.cg.shared.global [%0], [%1], 16;" :: "r"(dst), "l"(src))
#define CP_ASYNC16_Z(dst, src, sz) \
    asm volatile("cp.async.cg.shared.global [%0], [%1], 16, %2;" :: "r"(dst), "l"(src), "r"(sz))
#define CP_COMMIT()  asm volatile("cp.async.commit_group;" ::: "memory")
#define CP_WAIT2()   asm volatile("cp.async.wait_group 2;" ::: "memory")

__device__ __forceinline__ void mma_tf32(float* acc, const uint32_t* a, const uint32_t* b) {
    asm volatile(
        "mma.sync.aligned.m16n8k8.row.col.f32.tf32.tf32.f32 "
        "{%0,%1,%2,%3}, {%4,%5,%6,%7}, {%8,%9}, {%0,%1,%2,%3};"
        : "+f"(acc[0]), "+f"(acc[1]), "+f"(acc[2]), "+f"(acc[3])
        : "r"(a[0]), "r"(a[1]), "r"(a[2]), "r"(a[3]), "r"(b[0]), "r"(b[1]));
}

// ---------------- kernel ----------------
// CTA (blockIdx.x = p-tile, blockIdx.y = channel c):
//   out[b, c, p0:p0+128] = x[b, c, :] @ W[c, :, p0:p0+128] + bias[c, p0:p0+128]
// GEMM: M=64 (batch) x N=128 (p) x K=512, tf32 mma.sync, 3-stage cp.async pipeline.
__global__ void __launch_bounds__(256, 2)
pc_linear_mma(const float* __restrict__ x,
              const float* __restrict__ W,
              const float* __restrict__ bias,
              float* __restrict__ out)
{
    extern __shared__ float sm[];
    const uint32_t sbase = smem_to_u32(sm);

    const int tid  = threadIdx.x;
    const int lane = tid & 31;
    const int wid  = tid >> 5;
    const int gid  = lane >> 2;   // fragment group id (0..7)
    const int tig  = lane & 3;    // thread in group (0..3)
    const int wm   = wid >> 2;    // warp row   (0..1) -> m0 = wm*32
    const int wn   = wid & 3;     // warp col   (0..3) -> n0 = wn*32
    const int c    = blockIdx.y;
    const int p0   = blockIdx.x * BN;

    const float* xc = x + (size_t)c * D_K;                   // + b*(C*D) per row
    const float* Wc = W + (size_t)c * ((size_t)D_K * P_OUT); // [k][p]

    // ---- cp.async issue for one K-chunk into one stage ----
    auto issue = [&](int chunk, int stage) {
        const int k0 = chunk * BK;
        // A tile: x rows b=0..63, k0..k0+31  (64 x 128B rows)
        const uint32_t abase = sbase + (uint32_t)stage * A_STAGE_BYTES;
#pragma unroll
        for (int i = 0; i < 2; ++i) {
            const int id  = tid + i * 256;
            const int r   = id >> 3;          // batch row
            const int col = (id & 7) * 4;     // k offset
            const float* src = xc + (size_t)r * (C_CH * D_K) + k0 + col;
            CP_ASYNC16(abase + (uint32_t)(r * A_STRIDE + col) * 4, src);
        }
        // B tile: W rows k=k0..k0+31, p0..p0+127 (32 x 512B rows), zero-fill OOB p
        const uint32_t bbase = sbase + B_BASE + (uint32_t)stage * B_STAGE_BYTES;
#pragma unroll
        for (int j = 0; j < 4; ++j) {
            const int id  = tid + j * 256;
            const int r   = id >> 5;          // k row
            const int col = (id & 31) * 4;    // p offset
            const float* src = Wc + (size_t)(k0 + r) * P_OUT + p0 + col;
            const int sz = (p0 + col < P_OUT) ? 16 : 0;
            CP_ASYNC16_Z(bbase + (uint32_t)(r * B_STRIDE + col) * 4, src, sz);
        }
    };

    float acc[2][4][4];
#pragma unroll
    for (int mt = 0; mt < 2; ++mt)
#pragma unroll
        for (int nt = 0; nt < 4; ++nt)
#pragma unroll
            for (int q = 0; q < 4; ++q) acc[mt][nt][q] = 0.f;

    // ---- pipeline prologue ----
    issue(0, 0); CP_COMMIT();
    issue(1, 1); CP_COMMIT();

    // ---- mainloop ----
#pragma unroll 1
    for (int i = 0; i < KCHUNKS; ++i) {
        if (i + 2 < KCHUNKS) issue(i + 2, (i + 2) % STAGES);
        CP_COMMIT();              // commit every iter (possibly empty group)
        CP_WAIT2();               // chunk i landed
        __syncthreads();

        const float* As = sm + (size_t)(i % STAGES) * (A_STAGE_BYTES / 4);
        const float* Bs = sm + (B_BASE / 4) + (size_t)(i % STAGES) * (B_STAGE_BYTES / 4);

#pragma unroll
        for (int ks = 0; ks < 4; ++ks) {
            const int k = ks * 8;
            uint32_t af[2][4], bf[4][2];
#pragma unroll
            for (int mt = 0; mt < 2; ++mt) {
                const int r  = wm * 32 + mt * 16 + gid;
                const int cc = k + tig;
                af[mt][0] = f2tf32(As[r * A_STRIDE + cc]);
                af[mt][1] = f2tf32(As[(r + 8) * A_STRIDE + cc]);
                af[mt][2] = f2tf32(As[r * A_STRIDE + cc + 4]);
                af[mt][3] = f2tf32(As[(r + 8) * A_STRIDE + cc + 4]);
            }
#pragma unroll
            for (int nt = 0; nt < 4; ++nt) {
                const int col = wn * 32 + nt * 8 + gid;
                const int kb  = k + tig;
                bf[nt][0] = f2tf32(Bs[kb * B_STRIDE + col]);
                bf[nt][1] = f2tf32(Bs[(kb + 4) * B_STRIDE + col]);
            }
#pragma unroll
            for (int mt = 0; mt < 2; ++mt)
#pragma unroll
                for (int nt = 0; nt < 4; ++nt)
                    mma_tf32(acc[mt][nt], af[mt], bf[nt]);
        }
        __syncthreads();          // stage may be overwritten next iter
    }

    // ---- epilogue: D[b][p] + bias[c][p] -> out[b][c][p] ----
#pragma unroll
    for (int nt = 0; nt < 4; ++nt) {
        const int p = p0 + wn * 32 + nt * 8 + tig * 2;
        if (p < P_OUT) {
            const float2 bv = *(const float2*)(bias + (size_t)c * P_OUT + p);
#pragma unroll
            for (int mt = 0; mt < 2; ++mt) {
                const int b0r = wm * 32 + mt * 16 + gid;
                float2 v0 = make_float2(acc[mt][nt][0] + bv.x, acc[mt][nt][1] + bv.y);
                float2 v1 = make_float2(acc[mt][nt][2] + bv.x, acc[mt][nt][3] + bv.y);
                *(float2*)(out + ((size_t)b0r * C_CH + c) * P_OUT + p)       = v0;
                *(float2*)(out + ((size_t)(b0r + 8) * C_CH + c) * P_OUT + p) = v1;
            }
        }
    }
}

// ---------------- launch ----------------
extern "C" void kernel_launch(void* const* d_in, const int* in_sizes, int n_in,
                              void* d_out, int out_size) {
    const float* x  = (const float*)d_in[0];  // [64, 321, 512]
    const float* W  = (const float*)d_in[1];  // [321, 512, 720]
    const float* bi = (const float*)d_in[2];  // [321, 720]
    float* out      = (float*)d_out;          // [64, 321, 720]

    cudaFuncSetAttribute(pc_linear_mma,
                         cudaFuncAttributeMaxDynamicSharedMemorySize, SMEM_BYTES);
    dim3 grid((P_OUT + BN - 1) / BN, C_CH);   // 6 x 321 = 1926 CTAs
    pc_linear_mma<<<grid, 256, SMEM_BYTES>>>(x, W, bi, out);
}